// round 10
// baseline (speedup 1.0000x reference)
#include <cuda_runtime.h>
#include <cuda_bf16.h>
#include <cstdint>

#define NEG_INF (-1e10f)
#define INVLN2 1.4426950408889634f
#define LN2    0.6931471805599453f

// Problem constants
#define BB 32
#define TT 1000
#define HH 512
#define VV 2048
#define LL 100
#define SS 201
#define MROWS (BB*TT)          // 32000
#define MPAD  (MROWS + 64)     // padding for DP prefetch overrun

// fp8 scaling: X*4, W*16 -> logits scaled by 64; descale in epilogue
#define XSCALE 4.0f
#define WSCALE 16.0f
#define DESCALE (1.0f / 64.0f)

// gemm8 tiling
#define G8_ROW    40                    // u16 per SMEM row (32 data + 8 pad)
#define G8_TILE_B (128 * G8_ROW * 2)    // 10240 bytes per tile per buffer
#define G8_BUFS   4
#define G8_SMEM   (G8_BUFS * G8_TILE_B * 2)   // A + B rings = 81920 B

// ---------------- static device scratch (no allocation allowed) ----------------
__device__ __align__(16) static unsigned short g_X8[MROWS * HH / 2];     // eouts e4m3 pairs (*4)
__device__ __align__(16) static unsigned short g_W8[VV * HH / 2];        // W e4m3 pairs (*16)
__device__ __align__(16) static unsigned short g_Wlab8[BB * 128 * HH / 2]; // gathered label W e4m3 (*16)
__device__ __align__(16) static float          g_blab[BB * 128];         // gathered label bias
__device__ __align__(16) static float          g_sumexp[MPAD];           // per-row sum(exp(logit))
__device__ __align__(16) static float          g_lab[(size_t)MPAD * 128];// log2 softmax label probs

// ---------------- helpers ----------------
__device__ __forceinline__ unsigned smem_u32(const void* p) {
    return (unsigned)__cvta_generic_to_shared(p);
}

#define CP_ASYNC16(dst, src) \
    asm volatile("cp.async.ca.shared.global [%0], [%1], 16;\n" :: "r"(dst), "l"(src) : "memory")
#define CP_COMMIT() asm volatile("cp.async.commit_group;\n" ::: "memory")
#define CP_WAIT1()  asm volatile("cp.async.wait_group 1;\n" ::: "memory")
#define CP_WAIT2()  asm volatile("cp.async.wait_group 2;\n" ::: "memory")

__device__ __forceinline__ void ldmatrix_x4(unsigned* r, unsigned addr) {
    asm volatile("ldmatrix.sync.aligned.m8n8.x4.shared.b16 {%0,%1,%2,%3}, [%4];\n"
                 : "=r"(r[0]), "=r"(r[1]), "=r"(r[2]), "=r"(r[3]) : "r"(addr));
}

__device__ __forceinline__ void mma_fp8(float* d, const unsigned* a, unsigned b0, unsigned b1) {
    asm volatile("mma.sync.aligned.m16n8k32.row.col.f32.e4m3.e4m3.f32 "
                 "{%0,%1,%2,%3}, {%4,%5,%6,%7}, {%8,%9}, {%0,%1,%2,%3};\n"
                 : "+f"(d[0]), "+f"(d[1]), "+f"(d[2]), "+f"(d[3])
                 : "r"(a[0]), "r"(a[1]), "r"(a[2]), "r"(a[3]), "r"(b0), "r"(b1));
}

__device__ __forceinline__ float ex2f(float x) {
    float y; asm("ex2.approx.f32 %0, %1;" : "=f"(y) : "f"(x)); return y;
}
__device__ __forceinline__ float lg2f(float x) {
    float y; asm("lg2.approx.f32 %0, %1;" : "=f"(y) : "f"(x)); return y;
}

// pack two floats into e4m3x2 (lo = first elem, hi = second elem)
__device__ __forceinline__ unsigned short fp8pack(float lo, float hi) {
    unsigned short h;
    asm("cvt.rn.satfinite.e4m3x2.f32 %0, %1, %2;" : "=h"(h) : "f"(hi), "f"(lo));
    return h;
}

// ---------------- kernel 1: convert + gather + zero scratch/out ----------------
__global__ void prep_kernel(const float* __restrict__ eouts, const float* __restrict__ W,
                            const float* __restrict__ bias, const int* __restrict__ ys,
                            float* __restrict__ out, int out_size) {
    int i = blockIdx.x * blockDim.x + threadIdx.x;
    int stride = gridDim.x * blockDim.x;
    for (int k = i; k < MROWS * HH / 2; k += stride) {
        float2 v = ((const float2*)eouts)[k];
        g_X8[k] = fp8pack(v.x * XSCALE, v.y * XSCALE);
    }
    for (int k = i; k < VV * HH / 2; k += stride) {
        float2 v = ((const float2*)W)[k];
        g_W8[k] = fp8pack(v.x * WSCALE, v.y * WSCALE);
    }
    for (int k = i; k < BB * 128 * HH / 2; k += stride) {
        int kk2 = k & 255;              // u16 (pair) index within row
        int j   = (k >> 8) & 127;
        int b   = k >> 15;
        int v   = (j == 0) ? 0 : ((j <= LL) ? ys[b * LL + (j - 1)] : -1);
        if (v >= 0) {
            float2 ww = ((const float2*)(W + (size_t)v * HH))[kk2];
            g_Wlab8[k] = fp8pack(ww.x * WSCALE, ww.y * WSCALE);
        } else {
            g_Wlab8[k] = 0;
        }
    }
    for (int k = i; k < BB * 128; k += stride) {
        int j = k & 127;
        int b = k >> 7;
        int v = (j == 0) ? 0 : ((j <= LL) ? ys[b * LL + (j - 1)] : -1);
        g_blab[k] = (v >= 0) ? bias[v] : 0.0f;
    }
    for (int k = i; k < MPAD; k += stride) g_sumexp[k] = 0.0f;
    for (int k = i; k < out_size; k += stride) out[k] = 0.0f;
}

// ---------------- kernel 2: fp8 GEMM, deep ring, templated epilogue ----------------
// MODE 0: grid (250,16) full-V tile; epilogue: sum(exp) rows -> atomicAdd g_sumexp
// MODE 1: grid (8,32)  label tile per batch; epilogue: lp2 -> g_lab (fused log-softmax)
// Tiles whose rows are all t >= elens[b] produce dead data -> early exit.
template <int MODE>
__global__ __launch_bounds__(256)
void gemm8_kernel(const float* __restrict__ bias, const int* __restrict__ elens) {
    const int bx = blockIdx.x, by = blockIdx.y;

    // ---- dead-tile skip (uniform across block, before any barrier) ----
    if (MODE == 0) {
        int r0 = bx * 128;
        int b0 = r0 / 1000;
        int b1 = (r0 + 127) / 1000;
        if (b0 == b1 && (r0 - b0 * 1000) >= elens[b0]) return;
    } else {
        if (bx * 128 >= elens[by]) return;
    }

    extern __shared__ unsigned short sm8[];
    const unsigned As0 = smem_u32(sm8);
    const unsigned Bs0 = As0 + G8_BUFS * G8_TILE_B;

    const int tid = threadIdx.x, lane = tid & 31, wid = tid >> 5;
    const int wm = (wid & 3) * 32;
    const int wn = (wid >> 2) * 64;

    // staging: row = tid>>1 (0..127), 2 consecutive 16B chunks per thread
    const int ldrow = tid >> 1;
    const int ccol  = (tid & 1) * 16;       // u16 column of first chunk
    const unsigned short* Ag;
    const unsigned short* Bg;
    if (MODE == 0) {
        Ag = g_X8 + (size_t)(bx * 128 + ldrow) * 256 + ccol;
        Bg = g_W8 + (size_t)(by * 128 + ldrow) * 256 + ccol;
    } else {
        int t = bx * 128 + ldrow;
        if (t > TT - 1) t = TT - 1;         // clamp (values unused)
        Ag = g_X8    + (size_t)(by * TT + t) * 256 + ccol;
        Bg = g_Wlab8 + (size_t)(by * 128 + ldrow) * 256 + ccol;
    }
    const unsigned soff = (unsigned)(ldrow * G8_ROW + ccol) * 2;   // byte offset in tile

    auto stage = [&](int kt) {
        const unsigned bo = (unsigned)(kt & 3) * G8_TILE_B;
        const unsigned short* sa = Ag + kt * 32;
        const unsigned short* sb = Bg + kt * 32;
        CP_ASYNC16(As0 + bo + soff,      sa);
        CP_ASYNC16(As0 + bo + soff + 16, sa + 8);
        CP_ASYNC16(Bs0 + bo + soff,      sb);
        CP_ASYNC16(Bs0 + bo + soff + 16, sb + 8);
        CP_COMMIT();
    };

    float d[2][8][4];
#pragma unroll
    for (int mi = 0; mi < 2; mi++)
#pragma unroll
        for (int nj = 0; nj < 8; nj++)
#pragma unroll
            for (int q = 0; q < 4; q++) d[mi][nj][q] = 0.0f;

    unsigned aAddr[2], bAddr[4];
#pragma unroll
    for (int mi = 0; mi < 2; mi++)
        aAddr[mi] = As0 + (unsigned)((wm + mi * 16 + (lane & 15)) * G8_ROW + (lane >> 4) * 8) * 2;
#pragma unroll
    for (int np = 0; np < 4; np++) {
        int r = wn + np * 16 + (lane & 7) + ((lane >> 4) & 1) * 8;
        int c = ((lane >> 3) & 1) * 8;
        bAddr[np] = Bs0 + (unsigned)(r * G8_ROW + c) * 2;
    }

    stage(0); stage(1); stage(2);

#pragma unroll
    for (int kt = 0; kt < 8; kt++) {
        CP_WAIT2();
        __syncthreads();
        const unsigned bo = (unsigned)(kt & 3) * G8_TILE_B;
#pragma unroll
        for (int kq = 0; kq < 2; kq++) {
            const unsigned off = bo + kq * 32;
            unsigned ra[2][4], rb[4][4];
#pragma unroll
            for (int mi = 0; mi < 2; mi++) ldmatrix_x4(ra[mi], aAddr[mi] + off);
#pragma unroll
            for (int np = 0; np < 4; np++) ldmatrix_x4(rb[np], bAddr[np] + off);
#pragma unroll
            for (int mi = 0; mi < 2; mi++)
#pragma unroll
                for (int nj = 0; nj < 8; nj++) {
                    int np = nj >> 1;
                    unsigned b0 = (nj & 1) ? rb[np][2] : rb[np][0];
                    unsigned b1 = (nj & 1) ? rb[np][3] : rb[np][1];
                    mma_fp8(d[mi][nj], ra[mi], b0, b1);
                }
        }
        if (kt + 3 < 8) stage(kt + 3); else CP_COMMIT();
    }

    if (MODE == 0) {
        // row sums of exp(logit) in log2 domain; descale fp8 product by 1/64
        const float dsc = INVLN2 * DESCALE;
#pragma unroll
        for (int mi = 0; mi < 2; mi++) {
            float se0 = 0.0f, se1 = 0.0f;
            int r = bx * 128 + wm + mi * 16 + (lane >> 2);
#pragma unroll
            for (int nj = 0; nj < 8; nj++) {
                int c = by * 128 + wn + nj * 8 + (lane & 3) * 2;
                float b0 = __ldg(&bias[c]) * INVLN2;
                float b1 = __ldg(&bias[c + 1]) * INVLN2;
                se0 += ex2f(fmaf(d[mi][nj][0], dsc, b0)) + ex2f(fmaf(d[mi][nj][1], dsc, b1));
                se1 += ex2f(fmaf(d[mi][nj][2], dsc, b0)) + ex2f(fmaf(d[mi][nj][3], dsc, b1));
            }
            se0 += __shfl_xor_sync(0xffffffffu, se0, 1);
            se0 += __shfl_xor_sync(0xffffffffu, se0, 2);
            se1 += __shfl_xor_sync(0xffffffffu, se1, 1);
            se1 += __shfl_xor_sync(0xffffffffu, se1, 2);
            if ((lane & 3) == 0) {
                atomicAdd(&g_sumexp[r], se0);
                atomicAdd(&g_sumexp[r + 8], se1);
            }
        }
    } else {
        // fused log-softmax: lp2 = (d/64 + blab)/ln2 - log2(sumexp)
#pragma unroll
        for (int mi = 0; mi < 2; mi++) {
            int trow = bx * 128 + wm + mi * 16 + (lane >> 2);
            float ls0 = 0.0f, ls1 = 0.0f;
            if (trow < TT)     ls0 = lg2f(__ldg(&g_sumexp[by * TT + trow]));
            if (trow + 8 < TT) ls1 = lg2f(__ldg(&g_sumexp[by * TT + trow + 8]));
#pragma unroll
            for (int nj = 0; nj < 8; nj++) {
                int c = wn + nj * 8 + (lane & 3) * 2;
                float bl0 = g_blab[by * 128 + c];
                float bl1 = g_blab[by * 128 + c + 1];
                if (trow < TT) {
                    float2 v = make_float2(
                        fmaf(fmaf(d[mi][nj][0], DESCALE, bl0), INVLN2, -ls0),
                        fmaf(fmaf(d[mi][nj][1], DESCALE, bl1), INVLN2, -ls0));
                    *(float2*)&g_lab[(size_t)(by * TT + trow) * 128 + c] = v;
                }
                if (trow + 8 < TT) {
                    float2 v = make_float2(
                        fmaf(fmaf(d[mi][nj][2], DESCALE, bl0), INVLN2, -ls1),
                        fmaf(fmaf(d[mi][nj][3], DESCALE, bl1), INVLN2, -ls1));
                    *(float2*)&g_lab[(size_t)(by * TT + trow + 8) * 128 + c] = v;
                }
            }
        }
    }
}

// ---------------- kernel 3: CTC forward DP — fused quad-step trapezoid ----------------
// 13 warps (416 thr); warp w holds states s = 16w + lane - 16 (halo 16).
// Two fused 4-frame quad-steps per barrier (8 frames / commit).
// Quad-step: shfl alpha up 1..8, one local max m (offsets 5..8 gated by EXACT
// 4-step reachability), then 4 linear-domain substeps in registers, one lg2.
__global__ __launch_bounds__(416)
void ctc_dp_kernel(const int* __restrict__ ys, const int* __restrict__ elens,
                   const int* __restrict__ ylens, float* __restrict__ out) {
    const int b    = blockIdx.x;
    const int tid  = threadIdx.x;
    const int lane = tid & 31;
    const int w    = tid >> 5;              // 0..12
    const int s    = w * 16 + lane - 16;    // -16..207

    __shared__ float Asd[2][208];
    __shared__ float qbuf[2][24][128];

    const int ylen = ylens[b];
    const int tend = elens[b] - 1;

    const bool in_s  = (s >= 0 && s <= 200);
    const bool valid = in_s && (s <= 2 * ylen);

    const int sc0 = min(max(s, 0), 200);
    const int li0 = (sc0 & 1) ? ((sc0 >> 1) + 1) : 0;

    auto skip_of = [&](int x) -> float {
        if ((x & 1) && x >= 3 && x <= 200) {
            int h = x >> 1;
            return (ys[b * LL + h] != ys[b * LL + h - 1]) ? 1.0f : 0.0f;
        }
        return 0.0f;
    };
    float skv[7];
#pragma unroll
    for (int k = 0; k < 7; k++) skv[k] = skip_of(s - k);
    const bool k0 = skv[0] != 0.f, k1 = skv[1] != 0.f, k2 = skv[2] != 0.f,
               k3 = skv[3] != 0.f, k4 = skv[4] != 0.f, k5 = skv[5] != 0.f,
               k6 = skv[6] != 0.f;
    // exact 4-step reachability of source offsets 5..8 (path enumeration)
    const bool r5 = k0 | k1 | k2 | k3;
    const bool r6 = (k4 & k2) | (k4 & k1) | (k4 & k0) | (k3 & k1) | (k3 & k0) | (k2 & k0);
    const bool r7 = (k4 & k2 & k0) | (k5 & k2 & k0) | (k5 & k3 & k0) | (k5 & k3 & k1);
    const bool r8 = k6 & k4 & k2 & k0;

    // t = 0 init
    float a = NEG_INF;
    if (valid && s < 2) a = g_lab[(size_t)(b * TT) * 128 + li0];

    auto stage = [&](int cc, int bf) {
        int t0 = 1 + cc * 24;
        const float4* src = (const float4*)(g_lab + (size_t)(b * TT + t0) * 128);
        unsigned dst = smem_u32(&qbuf[bf][0][0]);
        for (int idx = tid; idx < 768; idx += 416)
            CP_ASYNC16(dst + (unsigned)idx * 16u, src + idx);
        CP_COMMIT();
    };

    // fused four-frame step: frames f0..f0+3
    auto quad = [&](int f0, int bf) {
        float A1 = __shfl_up_sync(0xffffffffu, a, 1);
        float A2 = __shfl_up_sync(0xffffffffu, a, 2);
        float A3 = __shfl_up_sync(0xffffffffu, a, 3);
        float A4 = __shfl_up_sync(0xffffffffu, a, 4);
        float A5 = __shfl_up_sync(0xffffffffu, a, 5);
        float A6 = __shfl_up_sync(0xffffffffu, a, 6);
        float A7 = __shfl_up_sync(0xffffffffu, a, 7);
        float A8 = __shfl_up_sync(0xffffffffu, a, 8);

        float p0 = ex2f(qbuf[bf][f0][li0]);
        float p1 = ex2f(qbuf[bf][f0 + 1][li0]);
        float p2 = ex2f(qbuf[bf][f0 + 2][li0]);
        float p3 = ex2f(qbuf[bf][f0 + 3][li0]);
        float p0k1 = __shfl_up_sync(0xffffffffu, p0, 1);
        float p0k2 = __shfl_up_sync(0xffffffffu, p0, 2);
        float p0k3 = __shfl_up_sync(0xffffffffu, p0, 3);
        float p0k4 = __shfl_up_sync(0xffffffffu, p0, 4);
        float p0k5 = __shfl_up_sync(0xffffffffu, p0, 5);
        float p0k6 = __shfl_up_sync(0xffffffffu, p0, 6);
        float p1k1 = __shfl_up_sync(0xffffffffu, p1, 1);
        float p1k2 = __shfl_up_sync(0xffffffffu, p1, 2);
        float p1k3 = __shfl_up_sync(0xffffffffu, p1, 3);
        float p1k4 = __shfl_up_sync(0xffffffffu, p1, 4);
        float p2k1 = __shfl_up_sync(0xffffffffu, p2, 1);
        float p2k2 = __shfl_up_sync(0xffffffffu, p2, 2);

        float m = fmaxf(fmaxf(a, A1), fmaxf(A2, fmaxf(A3, A4)));
        if (r5) m = fmaxf(m, A5);
        if (r6) m = fmaxf(m, A6);
        if (r7) m = fmaxf(m, A7);
        if (r8) m = fmaxf(m, A8);

        float W0 = ex2f(a - m),  W1 = ex2f(A1 - m), W2 = ex2f(A2 - m);
        float W3 = ex2f(A3 - m), W4 = ex2f(A4 - m);
        float W5 = r5 ? ex2f(A5 - m) : 0.0f;
        float W6 = r6 ? ex2f(A6 - m) : 0.0f;
        float W7 = r7 ? ex2f(A7 - m) : 0.0f;
        float W8 = r8 ? ex2f(A8 - m) : 0.0f;

        // substep 1 (frame f0): window 9 -> 7
        float V0 = fmaf(skv[0], W2, W0 + W1) * p0;
        float V1 = fmaf(skv[1], W3, W1 + W2) * p0k1;
        float V2 = fmaf(skv[2], W4, W2 + W3) * p0k2;
        float V3 = fmaf(skv[3], W5, W3 + W4) * p0k3;
        float V4 = fmaf(skv[4], W6, W4 + W5) * p0k4;
        float V5 = fmaf(skv[5], W7, W5 + W6) * p0k5;
        float V6 = fmaf(skv[6], W8, W6 + W7) * p0k6;
        // substep 2 (frame f0+1): 7 -> 5
        float U0 = fmaf(skv[0], V2, V0 + V1) * p1;
        float U1 = fmaf(skv[1], V3, V1 + V2) * p1k1;
        float U2 = fmaf(skv[2], V4, V2 + V3) * p1k2;
        float U3 = fmaf(skv[3], V5, V3 + V4) * p1k3;
        float U4 = fmaf(skv[4], V6, V4 + V5) * p1k4;
        // substep 3 (frame f0+2): 5 -> 3
        float X0 = fmaf(skv[0], U2, U0 + U1) * p2;
        float X1 = fmaf(skv[1], U3, U1 + U2) * p2k1;
        float X2 = fmaf(skv[2], U4, U2 + U3) * p2k2;
        // substep 4 (frame f0+3): 3 -> 1
        float R  = fmaf(skv[0], X2, X0 + X1) * p3;

        float nv = fmaxf(m + lg2f(R), NEG_INF);
        a = valid ? nv : NEG_INF;
    };

    auto sstep = [&](int f0, int bf) {
        float a1 = __shfl_up_sync(0xffffffffu, a, 1);
        float a2 = __shfl_up_sync(0xffffffffu, a, 2);
        if (!k0) a2 = NEG_INF;
        float lp = qbuf[bf][f0][li0];
        float m  = fmaxf(a, fmaxf(a1, a2));
        float su = ex2f(a - m) + ex2f(a1 - m) + ex2f(a2 - m);
        float nv = fmaxf(m + lg2f(su) + lp, NEG_INF);
        a = valid ? nv : NEG_INF;
    };

    stage(0, 0);
    stage(1, 1);

    int wb = 0, lastwb = 0;
    int t = 1, c = 0;
    while (t <= tend) {
        CP_WAIT1();
        __syncthreads();
        const int bf = c & 1;
        const int nfr = min(24, tend - t + 1);
        int fr = 0;
        while (fr < nfr) {
            int rem = nfr - fr;
            int h;
            if (rem >= 8)      { quad(fr, bf); quad(fr + 4, bf); h = 16; fr += 8; }
            else if (rem >= 4) { quad(fr, bf);                   h = 8;  fr += 4; }
            else               { sstep(fr, bf);                  h = 2;  fr += 1; }
            if (lane >= h && in_s) Asd[wb][s] = a;   // overlapping commits bit-identical
            __syncthreads();
            a = in_s ? Asd[wb][s] : NEG_INF;
            lastwb = wb; wb ^= 1;
        }
        if (nfr == 24) stage(c + 2, bf);
        t += nfr; c++;
    }

    if (tid == 0) {
        float last = Asd[lastwb][2 * ylen];
        float prev = Asd[lastwb][2 * ylen - 1];
        float mm = fmaxf(last, prev);
        float l2v = mm + lg2f(ex2f(last - mm) + ex2f(prev - mm));
        float lnat = -l2v * LN2;
        if (!(lnat < -0.5f * NEG_INF)) lnat = 0.0f;   // zero_infinity
        atomicAdd(out, lnat * (1.0f / (float)BB));
    }
}

// ---------------- launch ----------------
extern "C" void kernel_launch(void* const* d_in, const int* in_sizes, int n_in,
                              void* d_out, int out_size) {
    const float* eouts = (const float*)d_in[0];
    const float* W     = (const float*)d_in[1];
    const float* bias  = (const float*)d_in[2];
    const int*   ys    = (const int*)d_in[3];
    const int*   elens = (const int*)d_in[4];
    const int*   ylens = (const int*)d_in[5];
    float* out = (float*)d_out;

    cudaFuncSetAttribute(gemm8_kernel<0>,
                         cudaFuncAttributeMaxDynamicSharedMemorySize, G8_SMEM);
    cudaFuncSetAttribute(gemm8_kernel<1>,
                         cudaFuncAttributeMaxDynamicSharedMemorySize, G8_SMEM);

    prep_kernel<<<2048, 256>>>(eouts, W, bias, ys, out, out_size);
    gemm8_kernel<0><<<dim3(250, 16), 256, G8_SMEM>>>(bias, elens);
    gemm8_kernel<1><<<dim3(8, 32), 256, G8_SMEM>>>(bias, elens);
    ctc_dp_kernel<<<BB, 416>>>(ys, elens, ylens, out);
}

// round 11
// speedup vs baseline: 1.1097x; 1.1097x over previous
#include <cuda_runtime.h>
#include <cuda_bf16.h>
#include <cstdint>

#define NEG_INF (-1e10f)
#define INVLN2 1.4426950408889634f
#define LN2    0.6931471805599453f

// Problem constants
#define BB 32
#define TT 1000
#define HH 512
#define VV 2048
#define LL 100
#define SS 201
#define MROWS (BB*TT)          // 32000
#define MPAD  (MROWS + 64)     // padding for DP prefetch overrun

// fp8 scaling: X*4, W*16 -> logits scaled by 64; descale in epilogue
#define XSCALE 4.0f
#define WSCALE 16.0f
#define DESCALE (1.0f / 64.0f)

// gemm8 tiling
#define G8_ROW    40                    // u16 per SMEM row (32 data + 8 pad)
#define G8_TILE_B (128 * G8_ROW * 2)    // 10240 bytes per tile per buffer
#define G8_BUFS   4
#define G8_SMEM   (G8_BUFS * G8_TILE_B * 2)   // A + B rings = 81920 B

// ---------------- static device scratch (no allocation allowed) ----------------
__device__ __align__(16) static unsigned short g_X8[MROWS * HH / 2];     // eouts e4m3 pairs (*4)
__device__ __align__(16) static unsigned short g_W8[VV * HH / 2];        // W e4m3 pairs (*16)
__device__ __align__(16) static unsigned short g_Wlab8[BB * 128 * HH / 2]; // gathered label W e4m3 (*16)
__device__ __align__(16) static float          g_blab[BB * 128];         // gathered label bias
__device__ __align__(16) static float          g_sumexp[MPAD];           // per-row sum(exp(logit))
__device__ __align__(16) static float          g_lab[(size_t)MPAD * 128];// log2 softmax label probs

// ---------------- helpers ----------------
__device__ __forceinline__ unsigned smem_u32(const void* p) {
    return (unsigned)__cvta_generic_to_shared(p);
}

#define CP_ASYNC16(dst, src) \
    asm volatile("cp.async.ca.shared.global [%0], [%1], 16;\n" :: "r"(dst), "l"(src) : "memory")
#define CP_COMMIT() asm volatile("cp.async.commit_group;\n" ::: "memory")
#define CP_WAIT1()  asm volatile("cp.async.wait_group 1;\n" ::: "memory")
#define CP_WAIT2()  asm volatile("cp.async.wait_group 2;\n" ::: "memory")

__device__ __forceinline__ void ldmatrix_x4(unsigned* r, unsigned addr) {
    asm volatile("ldmatrix.sync.aligned.m8n8.x4.shared.b16 {%0,%1,%2,%3}, [%4];\n"
                 : "=r"(r[0]), "=r"(r[1]), "=r"(r[2]), "=r"(r[3]) : "r"(addr));
}

__device__ __forceinline__ void mma_fp8(float* d, const unsigned* a, unsigned b0, unsigned b1) {
    asm volatile("mma.sync.aligned.m16n8k32.row.col.f32.e4m3.e4m3.f32 "
                 "{%0,%1,%2,%3}, {%4,%5,%6,%7}, {%8,%9}, {%0,%1,%2,%3};\n"
                 : "+f"(d[0]), "+f"(d[1]), "+f"(d[2]), "+f"(d[3])
                 : "r"(a[0]), "r"(a[1]), "r"(a[2]), "r"(a[3]), "r"(b0), "r"(b1));
}

__device__ __forceinline__ float ex2f(float x) {
    float y; asm("ex2.approx.f32 %0, %1;" : "=f"(y) : "f"(x)); return y;
}
__device__ __forceinline__ float lg2f(float x) {
    float y; asm("lg2.approx.f32 %0, %1;" : "=f"(y) : "f"(x)); return y;
}

// pack two floats into e4m3x2 (lo = first elem, hi = second elem)
__device__ __forceinline__ unsigned short fp8pack(float lo, float hi) {
    unsigned short h;
    asm("cvt.rn.satfinite.e4m3x2.f32 %0, %1, %2;" : "=h"(h) : "f"(hi), "f"(lo));
    return h;
}

// ---------------- kernel 1: convert + gather + zero scratch/out ----------------
// eouts rows with t >= elens[b] are dead (never read by surviving tiles' useful
// rows): skip read+convert. Stale X8 there is deterministic under graph replay.
__global__ void prep_kernel(const float* __restrict__ eouts, const float* __restrict__ W,
                            const float* __restrict__ bias, const int* __restrict__ ys,
                            const int* __restrict__ elens,
                            float* __restrict__ out, int out_size) {
    int i = blockIdx.x * blockDim.x + threadIdx.x;
    int stride = gridDim.x * blockDim.x;
    for (int k = i; k < MROWS * HH / 2; k += stride) {
        int row = k >> 8;               // 256 pairs per row
        int b   = row / TT;
        int t   = row - b * TT;
        if (t < elens[b]) {
            float2 v = ((const float2*)eouts)[k];
            g_X8[k] = fp8pack(v.x * XSCALE, v.y * XSCALE);
        }
    }
    for (int k = i; k < VV * HH / 2; k += stride) {
        float2 v = ((const float2*)W)[k];
        g_W8[k] = fp8pack(v.x * WSCALE, v.y * WSCALE);
    }
    for (int k = i; k < BB * 128 * HH / 2; k += stride) {
        int kk2 = k & 255;              // u16 (pair) index within row
        int j   = (k >> 8) & 127;
        int b   = k >> 15;
        int v   = (j == 0) ? 0 : ((j <= LL) ? ys[b * LL + (j - 1)] : -1);
        if (v >= 0) {
            float2 ww = ((const float2*)(W + (size_t)v * HH))[kk2];
            g_Wlab8[k] = fp8pack(ww.x * WSCALE, ww.y * WSCALE);
        } else {
            g_Wlab8[k] = 0;
        }
    }
    for (int k = i; k < BB * 128; k += stride) {
        int j = k & 127;
        int b = k >> 7;
        int v = (j == 0) ? 0 : ((j <= LL) ? ys[b * LL + (j - 1)] : -1);
        g_blab[k] = (v >= 0) ? bias[v] : 0.0f;
    }
    for (int k = i; k < MPAD; k += stride) g_sumexp[k] = 0.0f;
    for (int k = i; k < out_size; k += stride) out[k] = 0.0f;
}

// ---------------- kernel 2: fp8 GEMM, deep ring, templated epilogue ----------------
// MODE 0: grid (250,16) full-V tile; epilogue: sum(exp) rows -> atomicAdd g_sumexp
// MODE 1: grid (8,32)  label tile per batch; epilogue: lp2 -> g_lab (fused log-softmax)
// Tiles whose rows are all t >= elens[b] produce dead data -> early exit.
template <int MODE>
__global__ __launch_bounds__(256)
void gemm8_kernel(const float* __restrict__ bias, const int* __restrict__ elens) {
    const int bx = blockIdx.x, by = blockIdx.y;

    // ---- dead-tile skip (uniform across block, before any barrier) ----
    if (MODE == 0) {
        int r0 = bx * 128;
        int b0 = r0 / 1000;
        int b1 = (r0 + 127) / 1000;
        if (b0 == b1 && (r0 - b0 * 1000) >= elens[b0]) return;
    } else {
        if (bx * 128 >= elens[by]) return;
    }

    extern __shared__ unsigned short sm8[];
    const unsigned As0 = smem_u32(sm8);
    const unsigned Bs0 = As0 + G8_BUFS * G8_TILE_B;

    const int tid = threadIdx.x, lane = tid & 31, wid = tid >> 5;
    const int wm = (wid & 3) * 32;
    const int wn = (wid >> 2) * 64;

    // staging: row = tid>>1 (0..127), 2 consecutive 16B chunks per thread
    const int ldrow = tid >> 1;
    const int ccol  = (tid & 1) * 16;       // u16 column of first chunk
    const unsigned short* Ag;
    const unsigned short* Bg;
    if (MODE == 0) {
        Ag = g_X8 + (size_t)(bx * 128 + ldrow) * 256 + ccol;
        Bg = g_W8 + (size_t)(by * 128 + ldrow) * 256 + ccol;
    } else {
        int t = bx * 128 + ldrow;
        if (t > TT - 1) t = TT - 1;         // clamp (values unused)
        Ag = g_X8    + (size_t)(by * TT + t) * 256 + ccol;
        Bg = g_Wlab8 + (size_t)(by * 128 + ldrow) * 256 + ccol;
    }
    const unsigned soff = (unsigned)(ldrow * G8_ROW + ccol) * 2;   // byte offset in tile

    auto stage = [&](int kt) {
        const unsigned bo = (unsigned)(kt & 3) * G8_TILE_B;
        const unsigned short* sa = Ag + kt * 32;
        const unsigned short* sb = Bg + kt * 32;
        CP_ASYNC16(As0 + bo + soff,      sa);
        CP_ASYNC16(As0 + bo + soff + 16, sa + 8);
        CP_ASYNC16(Bs0 + bo + soff,      sb);
        CP_ASYNC16(Bs0 + bo + soff + 16, sb + 8);
        CP_COMMIT();
    };

    float d[2][8][4];
#pragma unroll
    for (int mi = 0; mi < 2; mi++)
#pragma unroll
        for (int nj = 0; nj < 8; nj++)
#pragma unroll
            for (int q = 0; q < 4; q++) d[mi][nj][q] = 0.0f;

    unsigned aAddr[2], bAddr[4];
#pragma unroll
    for (int mi = 0; mi < 2; mi++)
        aAddr[mi] = As0 + (unsigned)((wm + mi * 16 + (lane & 15)) * G8_ROW + (lane >> 4) * 8) * 2;
#pragma unroll
    for (int np = 0; np < 4; np++) {
        int r = wn + np * 16 + (lane & 7) + ((lane >> 4) & 1) * 8;
        int c = ((lane >> 3) & 1) * 8;
        bAddr[np] = Bs0 + (unsigned)(r * G8_ROW + c) * 2;
    }

    stage(0); stage(1); stage(2);

#pragma unroll
    for (int kt = 0; kt < 8; kt++) {
        CP_WAIT2();
        __syncthreads();
        const unsigned bo = (unsigned)(kt & 3) * G8_TILE_B;
#pragma unroll
        for (int kq = 0; kq < 2; kq++) {
            const unsigned off = bo + kq * 32;
            unsigned ra[2][4], rb[4][4];
#pragma unroll
            for (int mi = 0; mi < 2; mi++) ldmatrix_x4(ra[mi], aAddr[mi] + off);
#pragma unroll
            for (int np = 0; np < 4; np++) ldmatrix_x4(rb[np], bAddr[np] + off);
#pragma unroll
            for (int mi = 0; mi < 2; mi++)
#pragma unroll
                for (int nj = 0; nj < 8; nj++) {
                    int np = nj >> 1;
                    unsigned b0 = (nj & 1) ? rb[np][2] : rb[np][0];
                    unsigned b1 = (nj & 1) ? rb[np][3] : rb[np][1];
                    mma_fp8(d[mi][nj], ra[mi], b0, b1);
                }
        }
        if (kt + 3 < 8) stage(kt + 3); else CP_COMMIT();
    }

    if (MODE == 0) {
        // row sums of exp(logit) in log2 domain; descale fp8 product by 1/64
        const float dsc = INVLN2 * DESCALE;
#pragma unroll
        for (int mi = 0; mi < 2; mi++) {
            float se0 = 0.0f, se1 = 0.0f;
            int r = bx * 128 + wm + mi * 16 + (lane >> 2);
#pragma unroll
            for (int nj = 0; nj < 8; nj++) {
                int c = by * 128 + wn + nj * 8 + (lane & 3) * 2;
                float b0 = __ldg(&bias[c]) * INVLN2;
                float b1 = __ldg(&bias[c + 1]) * INVLN2;
                se0 += ex2f(fmaf(d[mi][nj][0], dsc, b0)) + ex2f(fmaf(d[mi][nj][1], dsc, b1));
                se1 += ex2f(fmaf(d[mi][nj][2], dsc, b0)) + ex2f(fmaf(d[mi][nj][3], dsc, b1));
            }
            se0 += __shfl_xor_sync(0xffffffffu, se0, 1);
            se0 += __shfl_xor_sync(0xffffffffu, se0, 2);
            se1 += __shfl_xor_sync(0xffffffffu, se1, 1);
            se1 += __shfl_xor_sync(0xffffffffu, se1, 2);
            if ((lane & 3) == 0) {
                atomicAdd(&g_sumexp[r], se0);
                atomicAdd(&g_sumexp[r + 8], se1);
            }
        }
    } else {
        // fused log-softmax: lp2 = (d/64 + blab)/ln2 - log2(sumexp)
#pragma unroll
        for (int mi = 0; mi < 2; mi++) {
            int trow = bx * 128 + wm + mi * 16 + (lane >> 2);
            float ls0 = 0.0f, ls1 = 0.0f;
            if (trow < TT)     ls0 = lg2f(__ldg(&g_sumexp[by * TT + trow]));
            if (trow + 8 < TT) ls1 = lg2f(__ldg(&g_sumexp[by * TT + trow + 8]));
#pragma unroll
            for (int nj = 0; nj < 8; nj++) {
                int c = wn + nj * 8 + (lane & 3) * 2;
                float bl0 = g_blab[by * 128 + c];
                float bl1 = g_blab[by * 128 + c + 1];
                if (trow < TT) {
                    float2 v = make_float2(
                        fmaf(fmaf(d[mi][nj][0], DESCALE, bl0), INVLN2, -ls0),
                        fmaf(fmaf(d[mi][nj][1], DESCALE, bl1), INVLN2, -ls0));
                    *(float2*)&g_lab[(size_t)(by * TT + trow) * 128 + c] = v;
                }
                if (trow + 8 < TT) {
                    float2 v = make_float2(
                        fmaf(fmaf(d[mi][nj][2], DESCALE, bl0), INVLN2, -ls1),
                        fmaf(fmaf(d[mi][nj][3], DESCALE, bl1), INVLN2, -ls1));
                    *(float2*)&g_lab[(size_t)(by * TT + trow + 8) * 128 + c] = v;
                }
            }
        }
    }
}

// ---------------- kernel 3: CTC forward DP — fused double-step trapezoid (R8) ----------------
// 9 warps (288 thr); warp w holds states s = 24w + lane - 8 (halo 8).
// Two fused 2-frame steps per barrier group (4 frames / commit).
__global__ __launch_bounds__(288)
void ctc_dp_kernel(const int* __restrict__ ys, const int* __restrict__ elens,
                   const int* __restrict__ ylens, float* __restrict__ out) {
    const int b    = blockIdx.x;
    const int tid  = threadIdx.x;
    const int lane = tid & 31;
    const int w    = tid >> 5;              // 0..8
    const int s    = w * 24 + lane - 8;     // -8..215

    __shared__ float Asd[2][204];
    __shared__ float qbuf[2][24][128];

    const int ylen = ylens[b];
    const int tend = elens[b] - 1;

    const bool in_s  = (s >= 0 && s <= 200);
    const bool valid = in_s && (s <= 2 * ylen);

    const int sc0 = min(max(s, 0), 200);
    const int li0 = (sc0 & 1) ? ((sc0 >> 1) + 1) : 0;

    auto skip_of = [&](int x) -> float {
        if ((x & 1) && x >= 3 && x <= 200) {
            int h = x >> 1;
            return (ys[b * LL + h] != ys[b * LL + h - 1]) ? 1.0f : 0.0f;
        }
        return 0.0f;
    };
    const float sk0 = skip_of(s);
    const float sk1 = skip_of(s - 1);
    const float sk2 = skip_of(s - 2);
    const bool use3 = (sk0 != 0.0f) || (sk1 != 0.0f);   // a[s-3] reachable in 2 steps
    const bool use4 = (sk0 != 0.0f) && (sk2 != 0.0f);   // a[s-4] reachable in 2 steps

    // t = 0 init
    float a = NEG_INF;
    if (valid && s < 2) a = g_lab[(size_t)(b * TT) * 128 + li0];

    auto stage = [&](int cc, int bf) {
        int t0 = 1 + cc * 24;
        const float4* src = (const float4*)(g_lab + (size_t)(b * TT + t0) * 128);
        unsigned dst = smem_u32(&qbuf[bf][0][0]);
        for (int idx = tid; idx < 768; idx += 288)
            CP_ASYNC16(dst + (unsigned)idx * 16u, src + idx);
        CP_COMMIT();
    };

    // fused two-frame step: frames f0 (lp_t) and f0+1 (lp_{t+1})
    auto dstep = [&](int f0, int bf) {
        float a1 = __shfl_up_sync(0xffffffffu, a, 1);
        float a2 = __shfl_up_sync(0xffffffffu, a, 2);
        float a3 = __shfl_up_sync(0xffffffffu, a, 3);
        float a4 = __shfl_up_sync(0xffffffffu, a, 4);
        float a3u = use3 ? a3 : NEG_INF;
        float a4u = use4 ? a4 : NEG_INF;
        float lpA = qbuf[bf][f0][li0];
        float lpB = qbuf[bf][f0 + 1][li0];
        float P0 = ex2f(lpA);
        float P1 = __shfl_up_sync(0xffffffffu, P0, 1);
        float P2 = __shfl_up_sync(0xffffffffu, P0, 2);
        float m  = fmaxf(fmaxf(a, a1), fmaxf(fmaxf(a2, a3u), a4u));
        float q0 = ex2f(a - m),  q1 = ex2f(a1 - m), q2 = ex2f(a2 - m);
        float q3 = ex2f(a3u - m), q4 = ex2f(a4u - m);
        float I0 = fmaf(sk0, q2, q0 + q1);
        float I1 = fmaf(sk1, q3, q1 + q2);
        float I2 = fmaf(sk2, q4, q2 + q3);
        float S  = fmaf(P0, I0, fmaf(P1, I1, sk0 * P2 * I2));
        float nv = fmaxf(m + lg2f(S) + lpB, NEG_INF);
        a = valid ? nv : NEG_INF;
    };

    auto sstep = [&](int f0, int bf) {
        float a1 = __shfl_up_sync(0xffffffffu, a, 1);
        float a2 = __shfl_up_sync(0xffffffffu, a, 2);
        if (sk0 == 0.0f) a2 = NEG_INF;
        float lp = qbuf[bf][f0][li0];
        float m  = fmaxf(a, fmaxf(a1, a2));
        float su = ex2f(a - m) + ex2f(a1 - m) + ex2f(a2 - m);
        float nv = fmaxf(m + lg2f(su) + lp, NEG_INF);
        a = valid ? nv : NEG_INF;
    };

    stage(0, 0);
    stage(1, 1);

    int wb = 0, lastwb = 0;
    int t = 1, c = 0;
    while (t <= tend) {
        CP_WAIT1();
        __syncthreads();
        const int bf = c & 1;
        const int nfr = min(24, tend - t + 1);
        int fr = 0;
        while (fr < nfr) {
            int rem = nfr - fr;
            int h;
            if (rem >= 4)      { dstep(fr, bf); dstep(fr + 2, bf); h = 8; fr += 4; }
            else if (rem >= 2) { dstep(fr, bf);                    h = 4; fr += 2; }
            else               { sstep(fr, bf);                    h = 2; fr += 1; }
            if (lane >= h && in_s) Asd[wb][s] = a;   // overlapping commits bit-identical
            __syncthreads();
            a = in_s ? Asd[wb][s] : NEG_INF;
            lastwb = wb; wb ^= 1;
        }
        if (nfr == 24) stage(c + 2, bf);
        t += nfr; c++;
    }

    if (tid == 0) {
        float last = Asd[lastwb][2 * ylen];
        float prev = Asd[lastwb][2 * ylen - 1];
        float mm = fmaxf(last, prev);
        float l2v = mm + lg2f(ex2f(last - mm) + ex2f(prev - mm));
        float lnat = -l2v * LN2;
        if (!(lnat < -0.5f * NEG_INF)) lnat = 0.0f;   // zero_infinity
        atomicAdd(out, lnat * (1.0f / (float)BB));
    }
}

// ---------------- launch ----------------
extern "C" void kernel_launch(void* const* d_in, const int* in_sizes, int n_in,
                              void* d_out, int out_size) {
    const float* eouts = (const float*)d_in[0];
    const float* W     = (const float*)d_in[1];
    const float* bias  = (const float*)d_in[2];
    const int*   ys    = (const int*)d_in[3];
    const int*   elens = (const int*)d_in[4];
    const int*   ylens = (const int*)d_in[5];
    float* out = (float*)d_out;

    cudaFuncSetAttribute(gemm8_kernel<0>,
                         cudaFuncAttributeMaxDynamicSharedMemorySize, G8_SMEM);
    cudaFuncSetAttribute(gemm8_kernel<1>,
                         cudaFuncAttributeMaxDynamicSharedMemorySize, G8_SMEM);

    prep_kernel<<<2048, 256>>>(eouts, W, bias, ys, elens, out, out_size);
    gemm8_kernel<0><<<dim3(250, 16), 256, G8_SMEM>>>(bias, elens);
    gemm8_kernel<1><<<dim3(8, 32), 256, G8_SMEM>>>(bias, elens);
    ctc_dp_kernel<<<BB, 288>>>(ys, elens, ylens, out);
}

// round 12
// speedup vs baseline: 1.2226x; 1.1018x over previous
#include <cuda_runtime.h>
#include <cuda_bf16.h>
#include <cstdint>

#define NEG_INF (-1e10f)
#define INVLN2 1.4426950408889634f
#define LN2    0.6931471805599453f

// Problem constants
#define BB 32
#define TT 1000
#define HH 512
#define VV 2048
#define LL 100
#define SS 201
#define MROWS (BB*TT)          // 32000
#define MPAD  (MROWS + 64)     // padding for DP prefetch overrun

// fp8 scaling: X*4, W*16 -> logits scaled by 64; descale in epilogue
#define XSCALE 4.0f
#define WSCALE 16.0f
#define DESCALE (1.0f / 64.0f)

// gemm8 tiling
#define G8_ROW    40                    // u16 per SMEM row (32 data + 8 pad)
#define G8_TILE_B (128 * G8_ROW * 2)    // 10240 bytes per tile per buffer
#define G8_BUFS   4
#define G8_SMEM   (G8_BUFS * G8_TILE_B * 2)   // A + B rings = 81920 B (2 blocks/SM fit)

// ---------------- static device scratch (no allocation allowed) ----------------
__device__ __align__(16) static unsigned short g_X8[MROWS * HH / 2];     // eouts e4m3 pairs (*4)
__device__ __align__(16) static unsigned short g_W8[VV * HH / 2];        // W e4m3 pairs (*16)
__device__ __align__(16) static unsigned short g_Wlab8[BB * 128 * HH / 2]; // gathered label W e4m3 (*16)
__device__ __align__(16) static float          g_blab[BB * 128];         // gathered label bias
__device__ __align__(16) static float          g_sumexp[MPAD];           // per-row sum(exp(logit))
__device__ __align__(16) static float          g_lab[(size_t)MPAD * 128];// log2 softmax label probs

// ---------------- helpers ----------------
__device__ __forceinline__ unsigned smem_u32(const void* p) {
    return (unsigned)__cvta_generic_to_shared(p);
}

#define CP_ASYNC16(dst, src) \
    asm volatile("cp.async.ca.shared.global [%0], [%1], 16;\n" :: "r"(dst), "l"(src) : "memory")
#define CP_COMMIT() asm volatile("cp.async.commit_group;\n" ::: "memory")
#define CP_WAIT1()  asm volatile("cp.async.wait_group 1;\n" ::: "memory")
#define CP_WAIT2()  asm volatile("cp.async.wait_group 2;\n" ::: "memory")

__device__ __forceinline__ void ldmatrix_x4(unsigned* r, unsigned addr) {
    asm volatile("ldmatrix.sync.aligned.m8n8.x4.shared.b16 {%0,%1,%2,%3}, [%4];\n"
                 : "=r"(r[0]), "=r"(r[1]), "=r"(r[2]), "=r"(r[3]) : "r"(addr));
}

__device__ __forceinline__ void mma_fp8(float* d, const unsigned* a, unsigned b0, unsigned b1) {
    asm volatile("mma.sync.aligned.m16n8k32.row.col.f32.e4m3.e4m3.f32 "
                 "{%0,%1,%2,%3}, {%4,%5,%6,%7}, {%8,%9}, {%0,%1,%2,%3};\n"
                 : "+f"(d[0]), "+f"(d[1]), "+f"(d[2]), "+f"(d[3])
                 : "r"(a[0]), "r"(a[1]), "r"(a[2]), "r"(a[3]), "r"(b0), "r"(b1));
}

__device__ __forceinline__ float ex2f(float x) {
    float y; asm("ex2.approx.f32 %0, %1;" : "=f"(y) : "f"(x)); return y;
}
__device__ __forceinline__ float lg2f(float x) {
    float y; asm("lg2.approx.f32 %0, %1;" : "=f"(y) : "f"(x)); return y;
}

// pack two floats into e4m3x2 (lo = first elem, hi = second elem)
__device__ __forceinline__ unsigned short fp8pack(float lo, float hi) {
    unsigned short h;
    asm("cvt.rn.satfinite.e4m3x2.f32 %0, %1, %2;" : "=h"(h) : "f"(hi), "f"(lo));
    return h;
}

// ---------------- kernel 1: convert + gather + zero scratch/out ----------------
__global__ void prep_kernel(const float* __restrict__ eouts, const float* __restrict__ W,
                            const float* __restrict__ bias, const int* __restrict__ ys,
                            const int* __restrict__ elens,
                            float* __restrict__ out, int out_size) {
    int i = blockIdx.x * blockDim.x + threadIdx.x;
    int stride = gridDim.x * blockDim.x;
    for (int k = i; k < MROWS * HH / 2; k += stride) {
        int row = k >> 8;               // 256 pairs per row
        int b   = row / TT;
        int t   = row - b * TT;
        if (t < elens[b]) {
            float2 v = ((const float2*)eouts)[k];
            g_X8[k] = fp8pack(v.x * XSCALE, v.y * XSCALE);
        }
    }
    for (int k = i; k < VV * HH / 2; k += stride) {
        float2 v = ((const float2*)W)[k];
        g_W8[k] = fp8pack(v.x * WSCALE, v.y * WSCALE);
    }
    for (int k = i; k < BB * 128 * HH / 2; k += stride) {
        int kk2 = k & 255;              // u16 (pair) index within row
        int j   = (k >> 8) & 127;
        int b   = k >> 15;
        int v   = (j == 0) ? 0 : ((j <= LL) ? ys[b * LL + (j - 1)] : -1);
        if (v >= 0) {
            float2 ww = ((const float2*)(W + (size_t)v * HH))[kk2];
            g_Wlab8[k] = fp8pack(ww.x * WSCALE, ww.y * WSCALE);
        } else {
            g_Wlab8[k] = 0;
        }
    }
    for (int k = i; k < BB * 128; k += stride) {
        int j = k & 127;
        int b = k >> 7;
        int v = (j == 0) ? 0 : ((j <= LL) ? ys[b * LL + (j - 1)] : -1);
        g_blab[k] = (v >= 0) ? bias[v] : 0.0f;
    }
    for (int k = i; k < MPAD; k += stride) g_sumexp[k] = 0.0f;
    for (int k = i; k < out_size; k += stride) out[k] = 0.0f;
}

// ---------------- kernel 2: fp8 GEMM, deep ring, templated epilogue ----------------
// MODE 0: grid (250,16) full-V tile; epilogue: sum(exp) rows -> atomicAdd g_sumexp
// MODE 1: grid (8,32)  label tile per batch; epilogue: lp2 -> g_lab (fused log-softmax)
// Tiles whose rows are all t >= elens[b] produce dead data -> early exit.
// launch_bounds(256,2): allow 2 resident blocks/SM (2x80KB smem fits in 228KB).
template <int MODE>
__global__ __launch_bounds__(256, 2)
void gemm8_kernel(const float* __restrict__ bias, const int* __restrict__ elens) {
    const int bx = blockIdx.x, by = blockIdx.y;

    // ---- dead-tile skip (uniform across block, before any barrier) ----
    if (MODE == 0) {
        int r0 = bx * 128;
        int b0 = r0 / 1000;
        int b1 = (r0 + 127) / 1000;
        if (b0 == b1 && (r0 - b0 * 1000) >= elens[b0]) return;
    } else {
        if (bx * 128 >= elens[by]) return;
    }

    extern __shared__ unsigned short sm8[];
    const unsigned As0 = smem_u32(sm8);
    const unsigned Bs0 = As0 + G8_BUFS * G8_TILE_B;

    const int tid = threadIdx.x, lane = tid & 31, wid = tid >> 5;
    const int wm = (wid & 3) * 32;
    const int wn = (wid >> 2) * 64;

    // staging: row = tid>>1 (0..127), 2 consecutive 16B chunks per thread
    const int ldrow = tid >> 1;
    const int ccol  = (tid & 1) * 16;       // u16 column of first chunk
    const unsigned short* Ag;
    const unsigned short* Bg;
    if (MODE == 0) {
        Ag = g_X8 + (size_t)(bx * 128 + ldrow) * 256 + ccol;
        Bg = g_W8 + (size_t)(by * 128 + ldrow) * 256 + ccol;
    } else {
        int t = bx * 128 + ldrow;
        if (t > TT - 1) t = TT - 1;         // clamp (values unused)
        Ag = g_X8    + (size_t)(by * TT + t) * 256 + ccol;
        Bg = g_Wlab8 + (size_t)(by * 128 + ldrow) * 256 + ccol;
    }
    const unsigned soff = (unsigned)(ldrow * G8_ROW + ccol) * 2;   // byte offset in tile

    auto stage = [&](int kt) {
        const unsigned bo = (unsigned)(kt & 3) * G8_TILE_B;
        const unsigned short* sa = Ag + kt * 32;
        const unsigned short* sb = Bg + kt * 32;
        CP_ASYNC16(As0 + bo + soff,      sa);
        CP_ASYNC16(As0 + bo + soff + 16, sa + 8);
        CP_ASYNC16(Bs0 + bo + soff,      sb);
        CP_ASYNC16(Bs0 + bo + soff + 16, sb + 8);
        CP_COMMIT();
    };

    float d[2][8][4];
#pragma unroll
    for (int mi = 0; mi < 2; mi++)
#pragma unroll
        for (int nj = 0; nj < 8; nj++)
#pragma unroll
            for (int q = 0; q < 4; q++) d[mi][nj][q] = 0.0f;

    unsigned aAddr[2], bAddr[4];
#pragma unroll
    for (int mi = 0; mi < 2; mi++)
        aAddr[mi] = As0 + (unsigned)((wm + mi * 16 + (lane & 15)) * G8_ROW + (lane >> 4) * 8) * 2;
#pragma unroll
    for (int np = 0; np < 4; np++) {
        int r = wn + np * 16 + (lane & 7) + ((lane >> 4) & 1) * 8;
        int c = ((lane >> 3) & 1) * 8;
        bAddr[np] = Bs0 + (unsigned)(r * G8_ROW + c) * 2;
    }

    stage(0); stage(1); stage(2);

#pragma unroll
    for (int kt = 0; kt < 8; kt++) {
        CP_WAIT2();
        __syncthreads();
        const unsigned bo = (unsigned)(kt & 3) * G8_TILE_B;
#pragma unroll
        for (int kq = 0; kq < 2; kq++) {
            const unsigned off = bo + kq * 32;
            unsigned ra[2][4], rb[4][4];
#pragma unroll
            for (int mi = 0; mi < 2; mi++) ldmatrix_x4(ra[mi], aAddr[mi] + off);
#pragma unroll
            for (int np = 0; np < 4; np++) ldmatrix_x4(rb[np], bAddr[np] + off);
#pragma unroll
            for (int mi = 0; mi < 2; mi++)
#pragma unroll
                for (int nj = 0; nj < 8; nj++) {
                    int np = nj >> 1;
                    unsigned b0 = (nj & 1) ? rb[np][2] : rb[np][0];
                    unsigned b1 = (nj & 1) ? rb[np][3] : rb[np][1];
                    mma_fp8(d[mi][nj], ra[mi], b0, b1);
                }
        }
        if (kt + 3 < 8) stage(kt + 3); else CP_COMMIT();
    }

    if (MODE == 0) {
        // row sums of exp(logit) in log2 domain; descale fp8 product by 1/64
        const float dsc = INVLN2 * DESCALE;
#pragma unroll
        for (int mi = 0; mi < 2; mi++) {
            float se0 = 0.0f, se1 = 0.0f;
            int r = bx * 128 + wm + mi * 16 + (lane >> 2);
#pragma unroll
            for (int nj = 0; nj < 8; nj++) {
                int c = by * 128 + wn + nj * 8 + (lane & 3) * 2;
                float b0 = __ldg(&bias[c]) * INVLN2;
                float b1 = __ldg(&bias[c + 1]) * INVLN2;
                se0 += ex2f(fmaf(d[mi][nj][0], dsc, b0)) + ex2f(fmaf(d[mi][nj][1], dsc, b1));
                se1 += ex2f(fmaf(d[mi][nj][2], dsc, b0)) + ex2f(fmaf(d[mi][nj][3], dsc, b1));
            }
            se0 += __shfl_xor_sync(0xffffffffu, se0, 1);
            se0 += __shfl_xor_sync(0xffffffffu, se0, 2);
            se1 += __shfl_xor_sync(0xffffffffu, se1, 1);
            se1 += __shfl_xor_sync(0xffffffffu, se1, 2);
            if ((lane & 3) == 0) {
                atomicAdd(&g_sumexp[r], se0);
                atomicAdd(&g_sumexp[r + 8], se1);
            }
        }
    } else {
        // fused log-softmax: lp2 = (d/64 + blab)/ln2 - log2(sumexp)
#pragma unroll
        for (int mi = 0; mi < 2; mi++) {
            int trow = bx * 128 + wm + mi * 16 + (lane >> 2);
            float ls0 = 0.0f, ls1 = 0.0f;
            if (trow < TT)     ls0 = lg2f(__ldg(&g_sumexp[by * TT + trow]));
            if (trow + 8 < TT) ls1 = lg2f(__ldg(&g_sumexp[by * TT + trow + 8]));
#pragma unroll
            for (int nj = 0; nj < 8; nj++) {
                int c = wn + nj * 8 + (lane & 3) * 2;
                float bl0 = g_blab[by * 128 + c];
                float bl1 = g_blab[by * 128 + c + 1];
                if (trow < TT) {
                    float2 v = make_float2(
                        fmaf(fmaf(d[mi][nj][0], DESCALE, bl0), INVLN2, -ls0),
                        fmaf(fmaf(d[mi][nj][1], DESCALE, bl1), INVLN2, -ls0));
                    *(float2*)&g_lab[(size_t)(by * TT + trow) * 128 + c] = v;
                }
                if (trow + 8 < TT) {
                    float2 v = make_float2(
                        fmaf(fmaf(d[mi][nj][2], DESCALE, bl0), INVLN2, -ls1),
                        fmaf(fmaf(d[mi][nj][3], DESCALE, bl1), INVLN2, -ls1));
                    *(float2*)&g_lab[(size_t)(by * TT + trow + 8) * 128 + c] = v;
                }
            }
        }
    }
}

// ---------------- kernel 3: CTC forward DP — double-step trapezoid, 6-frame commits ----------
// 11 warps (352 thr); warp w holds states s = 20w + lane - 12 (halo 12).
// Three fused 2-frame steps per barrier group (6 frames / commit).
__global__ __launch_bounds__(352)
void ctc_dp_kernel(const int* __restrict__ ys, const int* __restrict__ elens,
                   const int* __restrict__ ylens, float* __restrict__ out) {
    const int b    = blockIdx.x;
    const int tid  = threadIdx.x;
    const int lane = tid & 31;
    const int w    = tid >> 5;              // 0..10
    const int s    = w * 20 + lane - 12;    // -12..219

    __shared__ float Asd[2][220];
    __shared__ float qbuf[2][24][128];

    const int ylen = ylens[b];
    const int tend = elens[b] - 1;

    const bool in_s  = (s >= 0 && s <= 200);
    const bool valid = in_s && (s <= 2 * ylen);

    const int sc0 = min(max(s, 0), 200);
    const int li0 = (sc0 & 1) ? ((sc0 >> 1) + 1) : 0;

    auto skip_of = [&](int x) -> float {
        if ((x & 1) && x >= 3 && x <= 200) {
            int h = x >> 1;
            return (ys[b * LL + h] != ys[b * LL + h - 1]) ? 1.0f : 0.0f;
        }
        return 0.0f;
    };
    const float sk0 = skip_of(s);
    const float sk1 = skip_of(s - 1);
    const float sk2 = skip_of(s - 2);
    const bool use3 = (sk0 != 0.0f) || (sk1 != 0.0f);   // a[s-3] reachable in 2 steps
    const bool use4 = (sk0 != 0.0f) && (sk2 != 0.0f);   // a[s-4] reachable in 2 steps

    // t = 0 init
    float a = NEG_INF;
    if (valid && s < 2) a = g_lab[(size_t)(b * TT) * 128 + li0];

    auto stage = [&](int cc, int bf) {
        int t0 = 1 + cc * 24;
        const float4* src = (const float4*)(g_lab + (size_t)(b * TT + t0) * 128);
        unsigned dst = smem_u32(&qbuf[bf][0][0]);
        for (int idx = tid; idx < 768; idx += 352)
            CP_ASYNC16(dst + (unsigned)idx * 16u, src + idx);
        CP_COMMIT();
    };

    // fused two-frame step: frames f0 (lp_t) and f0+1 (lp_{t+1})
    auto dstep = [&](int f0, int bf) {
        float a1 = __shfl_up_sync(0xffffffffu, a, 1);
        float a2 = __shfl_up_sync(0xffffffffu, a, 2);
        float a3 = __shfl_up_sync(0xffffffffu, a, 3);
        float a4 = __shfl_up_sync(0xffffffffu, a, 4);
        float a3u = use3 ? a3 : NEG_INF;
        float a4u = use4 ? a4 : NEG_INF;
        float lpA = qbuf[bf][f0][li0];
        float lpB = qbuf[bf][f0 + 1][li0];
        float P0 = ex2f(lpA);
        float P1 = __shfl_up_sync(0xffffffffu, P0, 1);
        float P2 = __shfl_up_sync(0xffffffffu, P0, 2);
        float m  = fmaxf(fmaxf(a, a1), fmaxf(fmaxf(a2, a3u), a4u));
        float q0 = ex2f(a - m),  q1 = ex2f(a1 - m), q2 = ex2f(a2 - m);
        float q3 = ex2f(a3u - m), q4 = ex2f(a4u - m);
        float I0 = fmaf(sk0, q2, q0 + q1);
        float I1 = fmaf(sk1, q3, q1 + q2);
        float I2 = fmaf(sk2, q4, q2 + q3);
        float S  = fmaf(P0, I0, fmaf(P1, I1, sk0 * P2 * I2));
        float nv = fmaxf(m + lg2f(S) + lpB, NEG_INF);
        a = valid ? nv : NEG_INF;
    };

    auto sstep = [&](int f0, int bf) {
        float a1 = __shfl_up_sync(0xffffffffu, a, 1);
        float a2 = __shfl_up_sync(0xffffffffu, a, 2);
        if (sk0 == 0.0f) a2 = NEG_INF;
        float lp = qbuf[bf][f0][li0];
        float m  = fmaxf(a, fmaxf(a1, a2));
        float su = ex2f(a - m) + ex2f(a1 - m) + ex2f(a2 - m);
        float nv = fmaxf(m + lg2f(su) + lp, NEG_INF);
        a = valid ? nv : NEG_INF;
    };

    stage(0, 0);
    stage(1, 1);

    int wb = 0, lastwb = 0;
    int t = 1, c = 0;
    while (t <= tend) {
        CP_WAIT1();
        __syncthreads();
        const int bf = c & 1;
        const int nfr = min(24, tend - t + 1);
        int fr = 0;
        while (fr < nfr) {
            int rem = nfr - fr;
            int h;
            if (rem >= 6)      { dstep(fr, bf); dstep(fr + 2, bf); dstep(fr + 4, bf);
                                 h = 12; fr += 6; }
            else if (rem >= 4) { dstep(fr, bf); dstep(fr + 2, bf); h = 8;  fr += 4; }
            else if (rem >= 2) { dstep(fr, bf);                    h = 4;  fr += 2; }
            else               { sstep(fr, bf);                    h = 2;  fr += 1; }
            if (lane >= h && in_s) Asd[wb][s] = a;   // overlapping commits bit-identical
            __syncthreads();
            a = in_s ? Asd[wb][s] : NEG_INF;
            lastwb = wb; wb ^= 1;
        }
        if (nfr == 24) stage(c + 2, bf);
        t += nfr; c++;
    }

    if (tid == 0) {
        float last = Asd[lastwb][2 * ylen];
        float prev = Asd[lastwb][2 * ylen - 1];
        float mm = fmaxf(last, prev);
        float l2v = mm + lg2f(ex2f(last - mm) + ex2f(prev - mm));
        float lnat = -l2v * LN2;
        if (!(lnat < -0.5f * NEG_INF)) lnat = 0.0f;   // zero_infinity
        atomicAdd(out, lnat * (1.0f / (float)BB));
    }
}

// ---------------- launch ----------------
extern "C" void kernel_launch(void* const* d_in, const int* in_sizes, int n_in,
                              void* d_out, int out_size) {
    const float* eouts = (const float*)d_in[0];
    const float* W     = (const float*)d_in[1];
    const float* bias  = (const float*)d_in[2];
    const int*   ys    = (const int*)d_in[3];
    const int*   elens = (const int*)d_in[4];
    const int*   ylens = (const int*)d_in[5];
    float* out = (float*)d_out;

    cudaFuncSetAttribute(gemm8_kernel<0>,
                         cudaFuncAttributeMaxDynamicSharedMemorySize, G8_SMEM);
    cudaFuncSetAttribute(gemm8_kernel<1>,
                         cudaFuncAttributeMaxDynamicSharedMemorySize, G8_SMEM);

    prep_kernel<<<2048, 256>>>(eouts, W, bias, ys, elens, out, out_size);
    gemm8_kernel<0><<<dim3(250, 16), 256, G8_SMEM>>>(bias, elens);
    gemm8_kernel<1><<<dim3(8, 32), 256, G8_SMEM>>>(bias, elens);
    ctc_dp_kernel<<<BB, 352>>>(ys, elens, ylens, out);
}

// round 13
// speedup vs baseline: 1.2559x; 1.0272x over previous
#include <cuda_runtime.h>
#include <cuda_bf16.h>
#include <cstdint>

#define NEG_INF (-1e10f)
#define INVLN2 1.4426950408889634f
#define LN2    0.6931471805599453f

// Problem constants
#define BB 32
#define TT 1000
#define HH 512
#define VV 2048
#define LL 100
#define SS 201
#define MROWS (BB*TT)          // 32000
#define MPAD  (MROWS + 64)     // padding for DP prefetch overrun

// fp8 scaling: X*4, W*16 -> logits scaled by 64; descale in epilogue
#define XSCALE 4.0f
#define WSCALE 16.0f
#define DESCALE (1.0f / 64.0f)

// gemm8 tiling
#define G8_ROW    40                    // u16 per SMEM row (32 data + 8 pad)
#define G8_TILE_B (128 * G8_ROW * 2)    // 10240 bytes per tile per buffer
#define G8_BUFS   4
#define G8_SMEM   (G8_BUFS * G8_TILE_B * 2)   // A + B rings = 81920 B

// ---------------- static device scratch (no allocation allowed) ----------------
__device__ __align__(16) static unsigned short g_X8[MROWS * HH / 2];     // eouts e4m3 pairs (*4)
__device__ __align__(16) static unsigned short g_W8[VV * HH / 2];        // W e4m3 pairs (*16)
__device__ __align__(16) static unsigned short g_Wlab8[BB * 128 * HH / 2]; // gathered label W e4m3 (*16)
__device__ __align__(16) static float          g_blab[BB * 128];         // gathered label bias
__device__ __align__(16) static float          g_sumexp[MPAD];           // per-row sum(exp(logit))
__device__ __align__(16) static float          g_lab[(size_t)MPAD * 128];// log2 softmax label probs
__device__                static int           g_done[BB * 8];           // per-(batch,tile) lab-ready flags

// ---------------- helpers ----------------
__device__ __forceinline__ unsigned smem_u32(const void* p) {
    return (unsigned)__cvta_generic_to_shared(p);
}

#define CP_ASYNC16(dst, src) \
    asm volatile("cp.async.ca.shared.global [%0], [%1], 16;\n" :: "r"(dst), "l"(src) : "memory")
#define CP_COMMIT() asm volatile("cp.async.commit_group;\n" ::: "memory")
#define CP_WAIT1()  asm volatile("cp.async.wait_group 1;\n" ::: "memory")
#define CP_WAIT2()  asm volatile("cp.async.wait_group 2;\n" ::: "memory")

__device__ __forceinline__ void ldmatrix_x4(unsigned* r, unsigned addr) {
    asm volatile("ldmatrix.sync.aligned.m8n8.x4.shared.b16 {%0,%1,%2,%3}, [%4];\n"
                 : "=r"(r[0]), "=r"(r[1]), "=r"(r[2]), "=r"(r[3]) : "r"(addr));
}

__device__ __forceinline__ void mma_fp8(float* d, const unsigned* a, unsigned b0, unsigned b1) {
    asm volatile("mma.sync.aligned.m16n8k32.row.col.f32.e4m3.e4m3.f32 "
                 "{%0,%1,%2,%3}, {%4,%5,%6,%7}, {%8,%9}, {%0,%1,%2,%3};\n"
                 : "+f"(d[0]), "+f"(d[1]), "+f"(d[2]), "+f"(d[3])
                 : "r"(a[0]), "r"(a[1]), "r"(a[2]), "r"(a[3]), "r"(b0), "r"(b1));
}

__device__ __forceinline__ float ex2f(float x) {
    float y; asm("ex2.approx.f32 %0, %1;" : "=f"(y) : "f"(x)); return y;
}
__device__ __forceinline__ float lg2f(float x) {
    float y; asm("lg2.approx.f32 %0, %1;" : "=f"(y) : "f"(x)); return y;
}

// pack two floats into e4m3x2 (lo = first elem, hi = second elem)
__device__ __forceinline__ unsigned short fp8pack(float lo, float hi) {
    unsigned short h;
    asm("cvt.rn.satfinite.e4m3x2.f32 %0, %1, %2;" : "=h"(h) : "f"(hi), "f"(lo));
    return h;
}

__device__ __forceinline__ unsigned pack8(float4 u, float4 v, float s, int sel) {
    // pack 4 floats (scaled) into 2 u16 fp8 pairs -> one u32
    unsigned short h0, h1;
    if (sel == 0) { h0 = fp8pack(u.x * s, u.y * s); h1 = fp8pack(u.z * s, u.w * s); }
    else          { h0 = fp8pack(v.x * s, v.y * s); h1 = fp8pack(v.z * s, v.w * s); }
    return (unsigned)h0 | ((unsigned)h1 << 16);
}

// ---------------- kernel 1: convert + gather + zero scratch/out ----------------
__global__ void prep_kernel(const float* __restrict__ eouts, const float* __restrict__ W,
                            const float* __restrict__ bias, const int* __restrict__ ys,
                            const int* __restrict__ elens,
                            float* __restrict__ out, int out_size) {
    int i = blockIdx.x * blockDim.x + threadIdx.x;
    int stride = gridDim.x * blockDim.x;
    // eouts: 8 floats per iteration (2x float4 -> uint2 of fp8)
    for (int k = i; k < MROWS * HH / 8; k += stride) {
        int row = k >> 6;               // 64 groups of 8 per 512-col row
        int b   = row / TT;
        int t   = row - b * TT;
        if (t < elens[b]) {
            float4 u = ((const float4*)eouts)[2 * k];
            float4 v = ((const float4*)eouts)[2 * k + 1];
            uint2 o;
            o.x = pack8(u, v, XSCALE, 0);
            o.y = pack8(u, v, XSCALE, 1);
            ((uint2*)g_X8)[k] = o;
        }
    }
    // W: 8 floats per iteration
    for (int k = i; k < VV * HH / 8; k += stride) {
        float4 u = ((const float4*)W)[2 * k];
        float4 v = ((const float4*)W)[2 * k + 1];
        uint2 o;
        o.x = pack8(u, v, WSCALE, 0);
        o.y = pack8(u, v, WSCALE, 1);
        ((uint2*)g_W8)[k] = o;
    }
    for (int k = i; k < BB * 128 * HH / 2; k += stride) {
        int kk2 = k & 255;              // u16 (pair) index within row
        int j   = (k >> 8) & 127;
        int b   = k >> 15;
        int v   = (j == 0) ? 0 : ((j <= LL) ? ys[b * LL + (j - 1)] : -1);
        if (v >= 0) {
            float2 ww = ((const float2*)(W + (size_t)v * HH))[kk2];
            g_Wlab8[k] = fp8pack(ww.x * WSCALE, ww.y * WSCALE);
        } else {
            g_Wlab8[k] = 0;
        }
    }
    for (int k = i; k < BB * 128; k += stride) {
        int j = k & 127;
        int b = k >> 7;
        int v = (j == 0) ? 0 : ((j <= LL) ? ys[b * LL + (j - 1)] : -1);
        g_blab[k] = (v >= 0) ? bias[v] : 0.0f;
    }
    for (int k = i; k < MPAD; k += stride) g_sumexp[k] = 0.0f;
    for (int k = i; k < BB * 8; k += stride) g_done[k] = 0;
    for (int k = i; k < out_size; k += stride) out[k] = 0.0f;
}

// ---------------- kernel 2: fp8 full-V GEMM (deep ring, occ 2) ----------------
// grid (250,16); epilogue: sum(exp) rows -> atomicAdd g_sumexp. Dead tiles skip.
__global__ __launch_bounds__(256, 2)
void gemm0_kernel(const float* __restrict__ bias, const int* __restrict__ elens) {
    const int bx = blockIdx.x, by = blockIdx.y;
    {
        int r0 = bx * 128;
        int b0 = r0 / 1000;
        int b1 = (r0 + 127) / 1000;
        if (b0 == b1 && (r0 - b0 * 1000) >= elens[b0]) return;
    }

    extern __shared__ unsigned short sm8[];
    const unsigned As0 = smem_u32(sm8);
    const unsigned Bs0 = As0 + G8_BUFS * G8_TILE_B;

    const int tid = threadIdx.x, lane = tid & 31, wid = tid >> 5;
    const int wm = (wid & 3) * 32;
    const int wn = (wid >> 2) * 64;

    const int ldrow = tid >> 1;
    const int ccol  = (tid & 1) * 16;
    const unsigned short* Ag = g_X8 + (size_t)(bx * 128 + ldrow) * 256 + ccol;
    const unsigned short* Bg = g_W8 + (size_t)(by * 128 + ldrow) * 256 + ccol;
    const unsigned soff = (unsigned)(ldrow * G8_ROW + ccol) * 2;

    auto stage = [&](int kt) {
        const unsigned bo = (unsigned)(kt & 3) * G8_TILE_B;
        const unsigned short* sa = Ag + kt * 32;
        const unsigned short* sb = Bg + kt * 32;
        CP_ASYNC16(As0 + bo + soff,      sa);
        CP_ASYNC16(As0 + bo + soff + 16, sa + 8);
        CP_ASYNC16(Bs0 + bo + soff,      sb);
        CP_ASYNC16(Bs0 + bo + soff + 16, sb + 8);
        CP_COMMIT();
    };

    float d[2][8][4];
#pragma unroll
    for (int mi = 0; mi < 2; mi++)
#pragma unroll
        for (int nj = 0; nj < 8; nj++)
#pragma unroll
            for (int q = 0; q < 4; q++) d[mi][nj][q] = 0.0f;

    unsigned aAddr[2], bAddr[4];
#pragma unroll
    for (int mi = 0; mi < 2; mi++)
        aAddr[mi] = As0 + (unsigned)((wm + mi * 16 + (lane & 15)) * G8_ROW + (lane >> 4) * 8) * 2;
#pragma unroll
    for (int np = 0; np < 4; np++) {
        int r = wn + np * 16 + (lane & 7) + ((lane >> 4) & 1) * 8;
        int c = ((lane >> 3) & 1) * 8;
        bAddr[np] = Bs0 + (unsigned)(r * G8_ROW + c) * 2;
    }

    stage(0); stage(1); stage(2);

#pragma unroll
    for (int kt = 0; kt < 8; kt++) {
        CP_WAIT2();
        __syncthreads();
        const unsigned bo = (unsigned)(kt & 3) * G8_TILE_B;
#pragma unroll
        for (int kq = 0; kq < 2; kq++) {
            const unsigned off = bo + kq * 32;
            unsigned ra[2][4], rb[4][4];
#pragma unroll
            for (int mi = 0; mi < 2; mi++) ldmatrix_x4(ra[mi], aAddr[mi] + off);
#pragma unroll
            for (int np = 0; np < 4; np++) ldmatrix_x4(rb[np], bAddr[np] + off);
#pragma unroll
            for (int mi = 0; mi < 2; mi++)
#pragma unroll
                for (int nj = 0; nj < 8; nj++) {
                    int np = nj >> 1;
                    unsigned b0 = (nj & 1) ? rb[np][2] : rb[np][0];
                    unsigned b1 = (nj & 1) ? rb[np][3] : rb[np][1];
                    mma_fp8(d[mi][nj], ra[mi], b0, b1);
                }
        }
        if (kt + 3 < 8) stage(kt + 3); else CP_COMMIT();
    }

    const float dsc = INVLN2 * DESCALE;
#pragma unroll
    for (int mi = 0; mi < 2; mi++) {
        float se0 = 0.0f, se1 = 0.0f;
        int r = bx * 128 + wm + mi * 16 + (lane >> 2);
#pragma unroll
        for (int nj = 0; nj < 8; nj++) {
            int c = by * 128 + wn + nj * 8 + (lane & 3) * 2;
            float b0 = __ldg(&bias[c]) * INVLN2;
            float b1 = __ldg(&bias[c + 1]) * INVLN2;
            se0 += ex2f(fmaf(d[mi][nj][0], dsc, b0)) + ex2f(fmaf(d[mi][nj][1], dsc, b1));
            se1 += ex2f(fmaf(d[mi][nj][2], dsc, b0)) + ex2f(fmaf(d[mi][nj][3], dsc, b1));
        }
        se0 += __shfl_xor_sync(0xffffffffu, se0, 1);
        se0 += __shfl_xor_sync(0xffffffffu, se0, 2);
        se1 += __shfl_xor_sync(0xffffffffu, se1, 1);
        se1 += __shfl_xor_sync(0xffffffffu, se1, 2);
        if ((lane & 3) == 0) {
            atomicAdd(&g_sumexp[r], se0);
            atomicAdd(&g_sumexp[r + 8], se1);
        }
    }
}

// ---------------- kernel 3: merged label-GEMM + CTC DP (producer/consumer) ----------------
// grid 288, block 352. Blocks 0..31: DP (batch = blockIdx). Blocks 32..287: label
// GEMM tiles, flat = blockIdx-32, bx = flat>>5 (frame tile), by = flat&31 (batch).
// Tile order puts bx=0 for ALL batches first so DP can start consuming early.
// gemm tiles publish g_done[by*8+bx] (fence+barrier+atomicExch); DP spins per chunk.
__global__ __launch_bounds__(352)
void label_dp_kernel(const int* __restrict__ ys, const int* __restrict__ elens,
                     const int* __restrict__ ylens, float* __restrict__ out) {
    extern __shared__ char smraw[];
    const int tid = threadIdx.x;

    if (blockIdx.x >= 32) {
        // ================= label GEMM role =================
        const int flat = blockIdx.x - 32;
        const int bx = flat >> 5;
        const int by = flat & 31;

        if (bx * 128 >= elens[by]) {
            if (tid == 0) { __threadfence(); atomicExch(&g_done[by * 8 + bx], 1); }
            return;
        }

        const unsigned As0 = smem_u32(smraw);
        const unsigned Bs0 = As0 + G8_BUFS * G8_TILE_B;
        const bool act = (tid < 256);
        const int lane = tid & 31, wid = tid >> 5;
        const int wm = (wid & 3) * 32;
        const int wn = (wid >> 2) * 64;

        const int ldrow = (tid >> 1) & 127;
        const int ccol  = (tid & 1) * 16;
        int trow_ld = bx * 128 + ldrow;
        if (trow_ld > TT - 1) trow_ld = TT - 1;
        const unsigned short* Ag = g_X8    + (size_t)(by * TT + trow_ld) * 256 + ccol;
        const unsigned short* Bg = g_Wlab8 + (size_t)(by * 128 + ldrow) * 256 + ccol;
        const unsigned soff = (unsigned)(ldrow * G8_ROW + ccol) * 2;

        auto stage = [&](int kt) {
            if (act) {
                const unsigned bo = (unsigned)(kt & 3) * G8_TILE_B;
                const unsigned short* sa = Ag + kt * 32;
                const unsigned short* sb = Bg + kt * 32;
                CP_ASYNC16(As0 + bo + soff,      sa);
                CP_ASYNC16(As0 + bo + soff + 16, sa + 8);
                CP_ASYNC16(Bs0 + bo + soff,      sb);
                CP_ASYNC16(Bs0 + bo + soff + 16, sb + 8);
                CP_COMMIT();
            }
        };

        float d[2][8][4];
#pragma unroll
        for (int mi = 0; mi < 2; mi++)
#pragma unroll
            for (int nj = 0; nj < 8; nj++)
#pragma unroll
                for (int q = 0; q < 4; q++) d[mi][nj][q] = 0.0f;

        unsigned aAddr[2], bAddr[4];
#pragma unroll
        for (int mi = 0; mi < 2; mi++)
            aAddr[mi] = As0 + (unsigned)((wm + mi * 16 + (lane & 15)) * G8_ROW + (lane >> 4) * 8) * 2;
#pragma unroll
        for (int np = 0; np < 4; np++) {
            int r = wn + np * 16 + (lane & 7) + ((lane >> 4) & 1) * 8;
            int c = ((lane >> 3) & 1) * 8;
            bAddr[np] = Bs0 + (unsigned)(r * G8_ROW + c) * 2;
        }

        stage(0); stage(1); stage(2);

#pragma unroll
        for (int kt = 0; kt < 8; kt++) {
            CP_WAIT2();               // threads >=256 have no groups: passes
            __syncthreads();
            if (act) {
                const unsigned bo = (unsigned)(kt & 3) * G8_TILE_B;
#pragma unroll
                for (int kq = 0; kq < 2; kq++) {
                    const unsigned off = bo + kq * 32;
                    unsigned ra[2][4], rb[4][4];
#pragma unroll
                    for (int mi = 0; mi < 2; mi++) ldmatrix_x4(ra[mi], aAddr[mi] + off);
#pragma unroll
                    for (int np = 0; np < 4; np++) ldmatrix_x4(rb[np], bAddr[np] + off);
#pragma unroll
                    for (int mi = 0; mi < 2; mi++)
#pragma unroll
                        for (int nj = 0; nj < 8; nj++) {
                            int np = nj >> 1;
                            unsigned b0 = (nj & 1) ? rb[np][2] : rb[np][0];
                            unsigned b1 = (nj & 1) ? rb[np][3] : rb[np][1];
                            mma_fp8(d[mi][nj], ra[mi], b0, b1);
                        }
                }
            }
            if (kt + 3 < 8) stage(kt + 3); else if (act) CP_COMMIT();
        }

        if (act) {
            // fused log-softmax: lp2 = (d/64 + blab)/ln2 - log2(sumexp)
#pragma unroll
            for (int mi = 0; mi < 2; mi++) {
                int trow = bx * 128 + wm + mi * 16 + (lane >> 2);
                float ls0 = 0.0f, ls1 = 0.0f;
                if (trow < TT)     ls0 = lg2f(__ldg(&g_sumexp[by * TT + trow]));
                if (trow + 8 < TT) ls1 = lg2f(__ldg(&g_sumexp[by * TT + trow + 8]));
#pragma unroll
                for (int nj = 0; nj < 8; nj++) {
                    int c = wn + nj * 8 + (lane & 3) * 2;
                    float bl0 = g_blab[by * 128 + c];
                    float bl1 = g_blab[by * 128 + c + 1];
                    if (trow < TT) {
                        float2 v = make_float2(
                            fmaf(fmaf(d[mi][nj][0], DESCALE, bl0), INVLN2, -ls0),
                            fmaf(fmaf(d[mi][nj][1], DESCALE, bl1), INVLN2, -ls0));
                        *(float2*)&g_lab[(size_t)(by * TT + trow) * 128 + c] = v;
                    }
                    if (trow + 8 < TT) {
                        float2 v = make_float2(
                            fmaf(fmaf(d[mi][nj][2], DESCALE, bl0), INVLN2, -ls1),
                            fmaf(fmaf(d[mi][nj][3], DESCALE, bl1), INVLN2, -ls1));
                        *(float2*)&g_lab[(size_t)(by * TT + trow + 8) * 128 + c] = v;
                    }
                }
            }
        }
        __threadfence();             // every thread fences its own g_lab stores
        __syncthreads();             // all fences done before flag
        if (tid == 0) atomicExch(&g_done[by * 8 + bx], 1);
        return;
    }

    // ================= CTC DP role (double-step trapezoid, 6-frame commits) =================
    const int b    = blockIdx.x;
    const int lane = tid & 31;
    const int w    = tid >> 5;              // 0..10
    const int s    = w * 20 + lane - 12;    // -12..219

    float* Asd = (float*)smraw;                       // [2][220]
    float* qb  = (float*)(smraw + 1792);              // [2][24][128]
    const unsigned qb0 = smem_u32(smraw) + 1792;

    const int ylen = ylens[b];
    const int tend = elens[b] - 1;

    const bool in_s  = (s >= 0 && s <= 200);
    const bool valid = in_s && (s <= 2 * ylen);

    const int sc0 = min(max(s, 0), 200);
    const int li0 = (sc0 & 1) ? ((sc0 >> 1) + 1) : 0;

    auto skip_of = [&](int x) -> float {
        if ((x & 1) && x >= 3 && x <= 200) {
            int h = x >> 1;
            return (ys[b * LL + h] != ys[b * LL + h - 1]) ? 1.0f : 0.0f;
        }
        return 0.0f;
    };
    const float sk0 = skip_of(s);
    const float sk1 = skip_of(s - 1);
    const float sk2 = skip_of(s - 2);
    const bool use3 = (sk0 != 0.0f) || (sk1 != 0.0f);
    const bool use4 = (sk0 != 0.0f) && (sk2 != 0.0f);

    // flag waiter: monotonic per-thread scan of this batch's 8 tile flags
    volatile int* dn = (volatile int*)(g_done + b * 8);
    int rdy = 0;
    auto waitTile = [&](int need) {
        if (rdy <= need) {
            while (rdy <= need) { if (dn[rdy] != 0) rdy++; }
            __threadfence();     // acquire: flag read -> data reads
        }
    };

    auto stage = [&](int cc, int bf) {
        int need = (24 * cc + 24) >> 7; if (need > 7) need = 7;
        waitTile(need);
        int t0 = 1 + cc * 24;
        const float4* src = (const float4*)(g_lab + (size_t)(b * TT + t0) * 128);
        unsigned dst = qb0 + (unsigned)bf * 12288u;
        for (int idx = tid; idx < 768; idx += 352)
            CP_ASYNC16(dst + (unsigned)idx * 16u, src + idx);
        CP_COMMIT();
    };

    // t = 0 init (needs tile 0)
    waitTile(0);
    float a = NEG_INF;
    if (valid && s < 2) a = g_lab[(size_t)(b * TT) * 128 + li0];

    auto dstep = [&](int f0, int bf) {
        float a1 = __shfl_up_sync(0xffffffffu, a, 1);
        float a2 = __shfl_up_sync(0xffffffffu, a, 2);
        float a3 = __shfl_up_sync(0xffffffffu, a, 3);
        float a4 = __shfl_up_sync(0xffffffffu, a, 4);
        float a3u = use3 ? a3 : NEG_INF;
        float a4u = use4 ? a4 : NEG_INF;
        float lpA = qb[(bf * 24 + f0) * 128 + li0];
        float lpB = qb[(bf * 24 + f0 + 1) * 128 + li0];
        float P0 = ex2f(lpA);
        float P1 = __shfl_up_sync(0xffffffffu, P0, 1);
        float P2 = __shfl_up_sync(0xffffffffu, P0, 2);
        float m  = fmaxf(fmaxf(a, a1), fmaxf(fmaxf(a2, a3u), a4u));
        float q0 = ex2f(a - m),  q1 = ex2f(a1 - m), q2 = ex2f(a2 - m);
        float q3 = ex2f(a3u - m), q4 = ex2f(a4u - m);
        float I0 = fmaf(sk0, q2, q0 + q1);
        float I1 = fmaf(sk1, q3, q1 + q2);
        float I2 = fmaf(sk2, q4, q2 + q3);
        float S  = fmaf(P0, I0, fmaf(P1, I1, sk0 * P2 * I2));
        float nv = fmaxf(m + lg2f(S) + lpB, NEG_INF);
        a = valid ? nv : NEG_INF;
    };

    auto sstep = [&](int f0, int bf) {
        float a1 = __shfl_up_sync(0xffffffffu, a, 1);
        float a2 = __shfl_up_sync(0xffffffffu, a, 2);
        if (sk0 == 0.0f) a2 = NEG_INF;
        float lp = qb[(bf * 24 + f0) * 128 + li0];
        float m  = fmaxf(a, fmaxf(a1, a2));
        float su = ex2f(a - m) + ex2f(a1 - m) + ex2f(a2 - m);
        float nv = fmaxf(m + lg2f(su) + lp, NEG_INF);
        a = valid ? nv : NEG_INF;
    };

    stage(0, 0);
    stage(1, 1);

    int wb = 0, lastwb = 0;
    int t = 1, c = 0;
    while (t <= tend) {
        CP_WAIT1();
        __syncthreads();
        const int bf = c & 1;
        const int nfr = min(24, tend - t + 1);
        int fr = 0;
        while (fr < nfr) {
            int rem = nfr - fr;
            int h;
            if (rem >= 6)      { dstep(fr, bf); dstep(fr + 2, bf); dstep(fr + 4, bf);
                                 h = 12; fr += 6; }
            else if (rem >= 4) { dstep(fr, bf); dstep(fr + 2, bf); h = 8;  fr += 4; }
            else if (rem >= 2) { dstep(fr, bf);                    h = 4;  fr += 2; }
            else               { sstep(fr, bf);                    h = 2;  fr += 1; }
            if (lane >= h && in_s) Asd[wb * 220 + s] = a;
            __syncthreads();
            a = in_s ? Asd[wb * 220 + s] : NEG_INF;
            lastwb = wb; wb ^= 1;
        }
        if (nfr == 24) stage(c + 2, bf);
        t += nfr; c++;
    }

    if (tid == 0) {
        float last = Asd[lastwb * 220 + 2 * ylen];
        float prev = Asd[lastwb * 220 + 2 * ylen - 1];
        float mm = fmaxf(last, prev);
        float l2v = mm + lg2f(ex2f(last - mm) + ex2f(prev - mm));
        float lnat = -l2v * LN2;
        if (!(lnat < -0.5f * NEG_INF)) lnat = 0.0f;   // zero_infinity
        atomicAdd(out, lnat * (1.0f / (float)BB));
    }
}

// ---------------- launch ----------------
extern "C" void kernel_launch(void* const* d_in, const int* in_sizes, int n_in,
                              void* d_out, int out_size) {
    const float* eouts = (const float*)d_in[0];
    const float* W     = (const float*)d_in[1];
    const float* bias  = (const float*)d_in[2];
    const int*   ys    = (const int*)d_in[3];
    const int*   elens = (const int*)d_in[4];
    const int*   ylens = (const int*)d_in[5];
    float* out = (float*)d_out;

    cudaFuncSetAttribute(gemm0_kernel,
                         cudaFuncAttributeMaxDynamicSharedMemorySize, G8_SMEM);
    cudaFuncSetAttribute(label_dp_kernel,
                         cudaFuncAttributeMaxDynamicSharedMemorySize, G8_SMEM);

    prep_kernel<<<2048, 256>>>(eouts, W, bias, ys, elens, out, out_size);
    gemm0_kernel<<<dim3(250, 16), 256, G8_SMEM>>>(bias, elens);
    label_dp_kernel<<<288, 352, G8_SMEM>>>(ys, elens, ylens, out);
}